// round 16
// baseline (speedup 1.0000x reference)
#include <cuda_runtime.h>

#define NV 32
#define N2 1024
#define N3 32768
#define N4 1048576
#define MB 16   // n*d = 2*8
#define SOUT 8

// r3 kept-axes order: 0=(i,j,k) 1=(i,j,l) 2=(i,k,l) 3=(j,k,l)
__device__ __align__(16) float g_r3[4][MB][N3];
__device__ __align__(16) float g_r2kl[MB][N2];
__device__ __align__(16) float g_r1raw[3][MB][NV];
__device__ __align__(16) float g_g3[4][2][SOUT][N3];
__device__ __align__(16) float g_g2[6][2][SOUT][N2];

// ---------------------------------------------------------------------------
// K1 (R15-proven): TWO jobs; job A software-pipelined smem transpose.
// ---------------------------------------------------------------------------
__global__ void __launch_bounds__(256) k_pass1(const float* __restrict__ x) {
    int t = threadIdx.x;
    if (blockIdx.x >= 512) {
        int b = blockIdx.x - 512;
        int m = b >> 5, j = b & 31;
        const float4* xb = reinterpret_cast<const float4*>(x)
                         + (size_t)(m * 32) * (N3 / 4) + j * 256 + t;
        float4 acc; acc.x = acc.y = acc.z = acc.w = 0.f;
#pragma unroll 8
        for (int i = 0; i < 32; ++i) {
            float4 v = __ldg(xb + (size_t)i * (N3 / 4));
            acc.x += v.x; acc.y += v.y; acc.z += v.z; acc.w += v.w;
        }
        reinterpret_cast<float4*>(g_r3[3][m])[j * 256 + t] = acc;
        return;
    }

    int m = blockIdx.x >> 5, i = blockIdx.x & 31;
    int k = t >> 3, l4 = t & 7;

    __shared__ float sbuf[2][4][32][36];

    float4 acc; acc.x = acc.y = acc.z = acc.w = 0.f;
    const float4* xb = reinterpret_cast<const float4*>(x) + (size_t)(m * 32 + i) * (N3 / 4);

    float4 vv[4];
#pragma unroll
    for (int u = 0; u < 4; ++u) vv[u] = __ldg(xb + u * 256 + t);

    for (int q = 0; q < 8; ++q) {
        int p = q & 1;
#pragma unroll
        for (int u = 0; u < 4; ++u) {
            float4 v = vv[u];
            acc.x += v.x; acc.y += v.y; acc.z += v.z; acc.w += v.w;
            *reinterpret_cast<float4*>(&sbuf[p][u][k][l4 * 4]) = v;
        }
        if (q < 7) {
#pragma unroll
            for (int u = 0; u < 4; ++u)
                vv[u] = __ldg(xb + (q + 1) * 1024 + u * 256 + t);
        }
        __syncthreads();

        int jo = q * 4;
        if (t < 128) {
            int j2 = t >> 5, k2 = t & 31;
            float4 s4; s4.x = s4.y = s4.z = s4.w = 0.f;
#pragma unroll
            for (int u = 0; u < 8; ++u) {
                float4 v = *reinterpret_cast<const float4*>(&sbuf[p][j2][k2][u * 4]);
                s4.x += v.x; s4.y += v.y; s4.z += v.z; s4.w += v.w;
            }
            g_r3[0][m][i * N2 + (jo + j2) * 32 + k2] = s4.x + s4.y + s4.z + s4.w;
        } else {
            int tt = t - 128;
            int j2 = tt >> 5, l = tt & 31;
            float s = 0.f;
#pragma unroll
            for (int u = 0; u < 32; ++u) s += sbuf[p][j2][u][l];
            g_r3[1][m][i * N2 + (jo + j2) * 32 + l] = s;
        }
    }

    reinterpret_cast<float4*>(g_r3[2][m])[i * 256 + t] = acc;
}

// ---------------------------------------------------------------------------
// K2 (R15-proven): Blocks 0..127: g3 channel mix. Blocks 128..191: r2/g2/r1.
// ---------------------------------------------------------------------------
__global__ void __launch_bounds__(256) k_mid(const float* __restrict__ coefs) {
    int t = threadIdx.x;
    if (blockIdx.x < 128) {
        __shared__ float C[4][4][64];
        for (int e = t; e < 1024; e += 256) {
            int a = e >> 8, b = (e >> 6) & 3, ds = e & 63;
            int d = ds >> 3, so = ds & 7;
            C[a][b][ds] = __ldg(&coefs[d * 552 + so * 69 + 52 + a * 4 + b]);
        }
        __syncthreads();

        int n = blockIdx.x >> 6, seg = blockIdx.x & 63;
        int tt2 = seg * 256 + t;

        float2 acc[32];
#pragma unroll
        for (int q = 0; q < 32; ++q) { acc[q].x = 0.f; acc[q].y = 0.f; }
#pragma unroll
        for (int a = 0; a < 4; ++a) {
            float2 vd[8];
#pragma unroll
            for (int d = 0; d < 8; ++d)
                vd[d] = __ldg(reinterpret_cast<const float2*>(g_r3[a][n * 8 + d]) + tt2);
#pragma unroll
            for (int b = 0; b < 4; ++b)
#pragma unroll
                for (int so = 0; so < 8; ++so) {
                    float sx = 0.f, sy = 0.f;
#pragma unroll
                    for (int d = 0; d < 8; ++d) {
                        float c = C[a][b][d * 8 + so];
                        sx += c * vd[d].x; sy += c * vd[d].y;
                    }
                    acc[b * 8 + so].x += sx; acc[b * 8 + so].y += sy;
                }
        }
#pragma unroll
        for (int b = 0; b < 4; ++b)
#pragma unroll
            for (int so = 0; so < 8; ++so)
                reinterpret_cast<float2*>(g_g3[b][n][so])[tt2] = acc[b * 8 + so];
    } else {
        int idx = blockIdx.x - 128;
        int n = idx >> 5, hi = idx & 31;
        int d = t >> 5, tl = t & 31;
        int m = n * 8 + d;

        __shared__ float4 CT[6][8][8][2];
        __shared__ float r2v[6][8][32];

        for (int e = t; e < 3072; e += 256) {
            int a = e >> 9, r = e & 511;
            int dd = r >> 6, so = (r >> 3) & 7, bq = r & 7;
            reinterpret_cast<float*>(CT)[((a * 8 + dd) * 8 + so) * 8 + bq] =
                (bq < 6) ? __ldg(&coefs[dd * 552 + so * 69 + 16 + a * 6 + bq]) : 0.f;
        }

        float s0, s1, s2, s3, s4, s5;
        {
            const float4* p = reinterpret_cast<const float4*>(g_r3[0][m] + hi * N2 + tl * 32);
            float4 a4 = {0.f, 0.f, 0.f, 0.f};
#pragma unroll
            for (int u = 0; u < 8; ++u) {
                float4 v = __ldg(p + u);
                a4.x += v.x; a4.y += v.y; a4.z += v.z; a4.w += v.w;
            }
            s0 = a4.x + a4.y + a4.z + a4.w;
        }
        s1 = s2 = s3 = s4 = s5 = 0.f;
#pragma unroll
        for (int u = 0; u < 32; ++u) {
            s1 += __ldg(&g_r3[0][m][hi * N2 + u * 32 + tl]);
            s2 += __ldg(&g_r3[1][m][hi * N2 + u * 32 + tl]);
            s3 += __ldg(&g_r3[0][m][u * N2 + hi * 32 + tl]);
            s4 += __ldg(&g_r3[1][m][u * N2 + hi * 32 + tl]);
            s5 += __ldg(&g_r3[2][m][u * N2 + hi * 32 + tl]);
        }

        float w0 = s0, w1 = s3, w2 = s5;
#pragma unroll
        for (int o = 16; o > 0; o >>= 1) {
            w0 += __shfl_down_sync(0xffffffffu, w0, o);
            w1 += __shfl_down_sync(0xffffffffu, w1, o);
            w2 += __shfl_down_sync(0xffffffffu, w2, o);
        }
        if (tl == 0) {
            g_r1raw[0][m][hi] = w0;
            g_r1raw[1][m][hi] = w1;
            g_r1raw[2][m][hi] = w2;
        }
        g_r2kl[m][hi * 32 + tl] = s5;

        r2v[0][d][tl] = s0; r2v[1][d][tl] = s1; r2v[2][d][tl] = s2;
        r2v[3][d][tl] = s3; r2v[4][d][tl] = s4; r2v[5][d][tl] = s5;
        __syncthreads();

        int tlp = t >> 3, so = t & 7;
        float b0 = 0.f, b1 = 0.f, b2 = 0.f, b3 = 0.f, b4 = 0.f, b5 = 0.f;
#pragma unroll
        for (int a = 0; a < 6; ++a)
#pragma unroll
            for (int dd = 0; dd < 8; ++dd) {
                float v = r2v[a][dd][tlp];
                float4 c0 = CT[a][dd][so][0];
                float4 c1 = CT[a][dd][so][1];
                b0 += v * c0.x; b1 += v * c0.y; b2 += v * c0.z;
                b3 += v * c0.w; b4 += v * c1.x; b5 += v * c1.y;
            }
        int tt = hi * 32 + tlp;
        g_g2[0][n][so][tt] = b0; g_g2[1][n][so][tt] = b1;
        g_g2[2][n][so][tt] = b2; g_g2[3][n][so][tt] = b3;
        g_g2[4][n][so][tt] = b4; g_g2[5][n][so][tt] = b5;
    }
}

// ---------------------------------------------------------------------------
// Kf: grid 512 = (n, i, j-octant of 4), __launch_bounds__(256,3) for 24
// warps/SM. Register-dieted inner loop: xv[8] batched, single acc float4
// per so (a4 folded at init). smem 48.5KB (x3 = 145.5KB <= 227).
// ---------------------------------------------------------------------------
__global__ void __launch_bounds__(256, 3) k_final(const float* __restrict__ x,
                                                  const float* __restrict__ coefs,
                                                  const float* __restrict__ bias,
                                                  float* __restrict__ out) {
    extern __shared__ __align__(16) char sm[];
    float4* sV  = reinterpret_cast<float4*>(sm);            // [8][256]
    float*  P4  = reinterpret_cast<float*>(sm + 32768);     // [4][8][32]
    float*  Q4  = reinterpret_cast<float*>(sm + 36864);     // [4][8][32]
    float*  sg1 = reinterpret_cast<float*>(sm + 40960);     // [4][8][32]
    float*  sr1 = reinterpret_cast<float*>(sm + 45056);     // [4][8][32]
    float*  cf  = reinterpret_cast<float*>(sm + 49152);     // [8][8]

    int bid = blockIdx.x;
    int n = bid >> 8, i = (bid >> 3) & 31, jo = bid & 7;
    int t = threadIdx.x, k = t >> 3, lq = t & 7;

    // ---- prologue 1: r1 values ----
    {
        int d = t >> 5, v = t & 31, m = n * 8 + d;
        float s = 0.f;
#pragma unroll
        for (int kk = 0; kk < 32; ++kk) s += __ldg(&g_r2kl[m][kk * 32 + v]);
        sr1[(3 * 8 + d) * 32 + v] = s;
        sr1[(0 * 8 + d) * 32 + v] = __ldg(&g_r1raw[0][m][v]);
        sr1[(1 * 8 + d) * 32 + v] = __ldg(&g_r1raw[1][m][v]);
        sr1[(2 * 8 + d) * 32 + v] = __ldg(&g_r1raw[2][m][v]);
    }
    if (t < 64) cf[t] = __ldg(&coefs[(t >> 3) * 552 + (t & 7) * 69 + 68]);
    __syncthreads();

    // ---- prologue 2: g1 mix ----
    {
        int so = t >> 5, v = t & 31;
        float b0 = 0.f, b1 = 0.f, b2 = 0.f, b3 = 0.f;
#pragma unroll
        for (int a = 0; a < 4; ++a)
#pragma unroll
            for (int d = 0; d < 8; ++d) {
                float val = sr1[(a * 8 + d) * 32 + v];
                const float* cp = &coefs[d * 552 + so * 69 + a * 4];
                b0 += __ldg(cp + 0) * val;
                b1 += __ldg(cp + 1) * val;
                b2 += __ldg(cp + 2) * val;
                b3 += __ldg(cp + 3) * val;
            }
        sg1[(0 * 8 + so) * 32 + v] = b0;
        sg1[(1 * 8 + so) * 32 + v] = b1;
        sg1[(2 * 8 + so) * 32 + v] = b2;
        sg1[(3 * 8 + so) * 32 + v] = b3;
    }
    __syncthreads();

    // ---- staging: sV + P4/Q4 (4 j's) ----
#pragma unroll
    for (int so = 0; so < 8; ++so) {
        float4 a = __ldg(reinterpret_cast<const float4*>(g_g3[2][n][so]) + i * 256 + t);
        float4 b = __ldg(reinterpret_cast<const float4*>(g_g2[5][n][so]) + t);
        a.x += b.x; a.y += b.y; a.z += b.z; a.w += b.w;
        sV[so * 256 + t] = a;
    }
    {
        int jj = t >> 6, kk = t & 31, sh = (t >> 5) & 1;
        int j = jo * 4 + jj, ij = i * 32 + j;
#pragma unroll
        for (int sop = 0; sop < 4; ++sop) {
            int so = sh * 4 + sop;
            P4[(jj * 8 + so) * 32 + kk] =
                  __ldg(&g_g3[0][n][so][ij * 32 + kk])
                + __ldg(&g_g2[3][n][so][j * 32 + kk])
                + __ldg(&g_g2[1][n][so][i * 32 + kk])
                + sg1[(2 * 8 + so) * 32 + kk]
                + __ldg(&g_g2[0][n][so][ij])
                + sg1[(0 * 8 + so) * 32 + i]
                + sg1[(1 * 8 + so) * 32 + j]
                + __ldg(&bias[so]);
            Q4[(jj * 8 + so) * 32 + kk] =
                  __ldg(&g_g3[1][n][so][ij * 32 + kk])
                + __ldg(&g_g2[4][n][so][j * 32 + kk])
                + __ldg(&g_g2[2][n][so][i * 32 + kk])
                + sg1[(3 * 8 + so) * 32 + kk];
        }
    }
    __syncthreads();

    const float4* xb = reinterpret_cast<const float4*>(x);
    float4* ob = reinterpret_cast<float4*>(out);

    for (int jj = 0; jj < 4; ++jj) {
        int j = jo * 4 + jj;
        int plane = (i * 32 + j) * 256 + t;

        float4 xv[8];
#pragma unroll
        for (int d = 0; d < 8; ++d)
            xv[d] = __ldg(xb + (size_t)(n * 8 + d) * (N4 / 4) + plane);

#pragma unroll
        for (int so = 0; so < 8; ++so) {
            float4 a4 = __ldg(reinterpret_cast<const float4*>(g_g3[3][n][so]) + j * 256 + t);
            float4 v1 = sV[so * 256 + t];
            float base = P4[(jj * 8 + so) * 32 + k];
            float4 q = *reinterpret_cast<const float4*>(&Q4[(jj * 8 + so) * 32 + lq * 4]);

            float4 acc;
            acc.x = base + q.x + v1.x + a4.x;
            acc.y = base + q.y + v1.y + a4.y;
            acc.z = base + q.z + v1.z + a4.z;
            acc.w = base + q.w + v1.w + a4.w;
#pragma unroll
            for (int d = 0; d < 8; ++d) {
                float c = cf[d * 8 + so];
                acc.x += c * xv[d].x;
                acc.y += c * xv[d].y;
                acc.z += c * xv[d].z;
                acc.w += c * xv[d].w;
            }
            ob[(size_t)(n * 8 + so) * (N4 / 4) + plane] = acc;
        }
    }
}

extern "C" void kernel_launch(void* const* d_in, const int* in_sizes, int n_in,
                              void* d_out, int out_size) {
    const float* x     = (const float*)d_in[0];
    const float* coefs = (const float*)d_in[1];
    const float* bias  = (const float*)d_in[2];
    float* out = (float*)d_out;

    cudaFuncSetAttribute(k_final, cudaFuncAttributeMaxDynamicSharedMemorySize, 49408);

    k_pass1<<<1024, 256>>>(x);           // r3[0..3] (job A pipelined)
    k_mid<<<192, 256>>>(coefs);          // g3 mix + g2/r1/r_kl
    k_final<<<512, 256, 49408>>>(x, coefs, bias, out);
}

// round 17
// speedup vs baseline: 1.2347x; 1.2347x over previous
#include <cuda_runtime.h>

#define NV 32
#define N2 1024
#define N3 32768
#define N4 1048576
#define MB 16   // n*d = 2*8
#define SOUT 8

// r3 kept-axes order: 0=(i,j,k) 1=(i,j,l) 2=(i,k,l) 3=(j,k,l)
__device__ __align__(16) float g_r3[4][MB][N3];
// raw r2 tables emitted by pass1: 0=r_ij 1=r_ik 2=r_il 3=r_jk 4=r_jl
__device__ __align__(16) float g_r2raw[5][MB][N2];
__device__ __align__(16) float g_r2kl[MB][N2];
__device__ __align__(16) float g_r1raw[3][MB][NV];
__device__ __align__(16) float g_g3[4][2][SOUT][N3];
__device__ __align__(16) float g_g2[6][2][SOUT][N2];

// ---------------------------------------------------------------------------
// K1: TWO jobs; job A pipelined smem transpose (R15) + r_ij/r_ik/r_il
// byproducts; job B (r_jkl) + r_jk/r_jl byproducts (one-time reductions).
// ---------------------------------------------------------------------------
__global__ void __launch_bounds__(256) k_pass1(const float* __restrict__ x) {
    int t = threadIdx.x;
    __shared__ float  sbuf[2][4][32][36];   // job A transpose (36.9KB)
    __shared__ float  scmb[8][32];          // job A end-combine (1KB)
    __shared__ float4 sjl[8][8];            // job B r_jl combine (0.5KB)

    if (blockIdx.x >= 512) {
        // ---- job B: (m,j) -> r3[3]=r_jkl, r_jk, r_jl ----
        int b = blockIdx.x - 512;
        int m = b >> 5, j = b & 31;
        int w = t >> 5, lane = t & 31;
        const float4* xb = reinterpret_cast<const float4*>(x)
                         + (size_t)(m * 32) * (N3 / 4) + j * 256 + t;
        float4 acc; acc.x = acc.y = acc.z = acc.w = 0.f;
#pragma unroll 8
        for (int i = 0; i < 32; ++i) {
            float4 v = __ldg(xb + (size_t)i * (N3 / 4));
            acc.x += v.x; acc.y += v.y; acc.z += v.z; acc.w += v.w;
        }
        reinterpret_cast<float4*>(g_r3[3][m])[j * 256 + t] = acc;

        // r_jk: sum over l within the 8-lane k-group
        float s = acc.x + acc.y + acc.z + acc.w;
        s += __shfl_down_sync(0xffffffffu, s, 4, 8);
        s += __shfl_down_sync(0xffffffffu, s, 2, 8);
        s += __shfl_down_sync(0xffffffffu, s, 1, 8);
        if ((lane & 7) == 0) g_r2raw[3][m][j * 32 + (t >> 3)] = s;

        // r_jl: per-warp column partial (over the warp's 4 k), combine in smem
        float4 c = acc;
        c.x += __shfl_xor_sync(0xffffffffu, c.x, 8);
        c.y += __shfl_xor_sync(0xffffffffu, c.y, 8);
        c.z += __shfl_xor_sync(0xffffffffu, c.z, 8);
        c.w += __shfl_xor_sync(0xffffffffu, c.w, 8);
        c.x += __shfl_xor_sync(0xffffffffu, c.x, 16);
        c.y += __shfl_xor_sync(0xffffffffu, c.y, 16);
        c.z += __shfl_xor_sync(0xffffffffu, c.z, 16);
        c.w += __shfl_xor_sync(0xffffffffu, c.w, 16);
        if (lane < 8) sjl[w][lane] = c;
        __syncthreads();
        if (t < 8) {
            float4 rv = sjl[0][t];
#pragma unroll
            for (int ww = 1; ww < 8; ++ww) {
                float4 cc = sjl[ww][t];
                rv.x += cc.x; rv.y += cc.y; rv.z += cc.z; rv.w += cc.w;
            }
            reinterpret_cast<float4*>(&g_r2raw[4][m][j * 32])[t] = rv;
        }
        return;
    }

    // ---- job A: (m,i) ----
    int m = blockIdx.x >> 5, i = blockIdx.x & 31;
    int k = t >> 3, l4 = t & 7;

    float4 acc; acc.x = acc.y = acc.z = acc.w = 0.f;
    float part = 0.f;   // warps 0-3: r_ik partial; warps 4-7: r_il partial
    const float4* xb = reinterpret_cast<const float4*>(x) + (size_t)(m * 32 + i) * (N3 / 4);

    float4 vv[4];
#pragma unroll
    for (int u = 0; u < 4; ++u) vv[u] = __ldg(xb + u * 256 + t);

    for (int q = 0; q < 8; ++q) {
        int p = q & 1;
#pragma unroll
        for (int u = 0; u < 4; ++u) {
            float4 v = vv[u];
            acc.x += v.x; acc.y += v.y; acc.z += v.z; acc.w += v.w;
            *reinterpret_cast<float4*>(&sbuf[p][u][k][l4 * 4]) = v;
        }
        if (q < 7) {
#pragma unroll
            for (int u = 0; u < 4; ++u)
                vv[u] = __ldg(xb + (q + 1) * 1024 + u * 256 + t);
        }
        __syncthreads();

        int jo = q * 4;
        if (t < 128) {
            // r_ijk + r_ij + r_ik partial
            int j2 = t >> 5, k2 = t & 31;
            float4 s4; s4.x = s4.y = s4.z = s4.w = 0.f;
#pragma unroll
            for (int u = 0; u < 8; ++u) {
                float4 v = *reinterpret_cast<const float4*>(&sbuf[p][j2][k2][u * 4]);
                s4.x += v.x; s4.y += v.y; s4.z += v.z; s4.w += v.w;
            }
            float rowsum = s4.x + s4.y + s4.z + s4.w;
            g_r3[0][m][i * N2 + (jo + j2) * 32 + k2] = rowsum;
            part += rowsum;                            // -> r_ik
            float rj = rowsum;                         // -> r_ij
            rj += __shfl_down_sync(0xffffffffu, rj, 16);
            rj += __shfl_down_sync(0xffffffffu, rj, 8);
            rj += __shfl_down_sync(0xffffffffu, rj, 4);
            rj += __shfl_down_sync(0xffffffffu, rj, 2);
            rj += __shfl_down_sync(0xffffffffu, rj, 1);
            if (k2 == 0) g_r2raw[0][m][i * 32 + jo + j2] = rj;
        } else {
            // r_ijl + r_il partial
            int tt = t - 128;
            int j2 = tt >> 5, l = tt & 31;
            float s = 0.f;
#pragma unroll
            for (int u = 0; u < 32; ++u) s += sbuf[p][j2][u][l];
            g_r3[1][m][i * N2 + (jo + j2) * 32 + l] = s;
            part += s;                                 // -> r_il
        }
    }

    // r_ikl (complete)
    reinterpret_cast<float4*>(g_r3[2][m])[i * 256 + t] = acc;

    // combine r_ik / r_il partials across the 4 warps of each half
    {
        int half = t >> 7;                    // 0: r_ik, 1: r_il
        int j2 = (t >> 5) & 3, c = t & 31;
        scmb[half * 4 + j2][c] = part;
    }
    __syncthreads();
    if (t < 32) {
        float s = scmb[0][t] + scmb[1][t] + scmb[2][t] + scmb[3][t];
        g_r2raw[1][m][i * 32 + t] = s;        // r_ik
    } else if (t < 64) {
        int l = t - 32;
        float s = scmb[4][l] + scmb[5][l] + scmb[6][l] + scmb[7][l];
        g_r2raw[2][m][i * 32 + l] = s;        // r_il
    }
}

// ---------------------------------------------------------------------------
// K2: Blocks 0..127: g3 channel mix (unchanged). Blocks 128..191: g2/r1 —
// now loads 5 precomputed r2 tables + computes only r_kl (32 loads).
// ---------------------------------------------------------------------------
__global__ void __launch_bounds__(256) k_mid(const float* __restrict__ coefs) {
    int t = threadIdx.x;
    if (blockIdx.x < 128) {
        __shared__ float C[4][4][64];
        for (int e = t; e < 1024; e += 256) {
            int a = e >> 8, b = (e >> 6) & 3, ds = e & 63;
            int d = ds >> 3, so = ds & 7;
            C[a][b][ds] = __ldg(&coefs[d * 552 + so * 69 + 52 + a * 4 + b]);
        }
        __syncthreads();

        int n = blockIdx.x >> 6, seg = blockIdx.x & 63;
        int tt2 = seg * 256 + t;

        float2 acc[32];
#pragma unroll
        for (int q = 0; q < 32; ++q) { acc[q].x = 0.f; acc[q].y = 0.f; }
#pragma unroll
        for (int a = 0; a < 4; ++a) {
            float2 vd[8];
#pragma unroll
            for (int d = 0; d < 8; ++d)
                vd[d] = __ldg(reinterpret_cast<const float2*>(g_r3[a][n * 8 + d]) + tt2);
#pragma unroll
            for (int b = 0; b < 4; ++b)
#pragma unroll
                for (int so = 0; so < 8; ++so) {
                    float sx = 0.f, sy = 0.f;
#pragma unroll
                    for (int d = 0; d < 8; ++d) {
                        float c = C[a][b][d * 8 + so];
                        sx += c * vd[d].x; sy += c * vd[d].y;
                    }
                    acc[b * 8 + so].x += sx; acc[b * 8 + so].y += sy;
                }
        }
#pragma unroll
        for (int b = 0; b < 4; ++b)
#pragma unroll
            for (int so = 0; so < 8; ++so)
                reinterpret_cast<float2*>(g_g3[b][n][so])[tt2] = acc[b * 8 + so];
    } else {
        int idx = blockIdx.x - 128;
        int n = idx >> 5, hi = idx & 31;
        int d = t >> 5, tl = t & 31;
        int m = n * 8 + d;

        __shared__ float4 CT[6][8][8][2];
        __shared__ float r2v[6][8][32];

        for (int e = t; e < 3072; e += 256) {
            int a = e >> 9, r = e & 511;
            int dd = r >> 6, so = (r >> 3) & 7, bq = r & 7;
            reinterpret_cast<float*>(CT)[((a * 8 + dd) * 8 + so) * 8 + bq] =
                (bq < 6) ? __ldg(&coefs[dd * 552 + so * 69 + 16 + a * 6 + bq]) : 0.f;
        }

        float s0 = __ldg(&g_r2raw[0][m][hi * 32 + tl]);   // r_ij
        float s1 = __ldg(&g_r2raw[1][m][hi * 32 + tl]);   // r_ik
        float s2 = __ldg(&g_r2raw[2][m][hi * 32 + tl]);   // r_il
        float s3 = __ldg(&g_r2raw[3][m][hi * 32 + tl]);   // r_jk
        float s4 = __ldg(&g_r2raw[4][m][hi * 32 + tl]);   // r_jl
        float s5 = 0.f;                                   // r_kl = sum_i r3[2]
#pragma unroll
        for (int u = 0; u < 32; ++u)
            s5 += __ldg(&g_r3[2][m][u * N2 + hi * 32 + tl]);

        float w0 = s0, w1 = s3, w2 = s5;
#pragma unroll
        for (int o = 16; o > 0; o >>= 1) {
            w0 += __shfl_down_sync(0xffffffffu, w0, o);
            w1 += __shfl_down_sync(0xffffffffu, w1, o);
            w2 += __shfl_down_sync(0xffffffffu, w2, o);
        }
        if (tl == 0) {
            g_r1raw[0][m][hi] = w0;
            g_r1raw[1][m][hi] = w1;
            g_r1raw[2][m][hi] = w2;
        }
        g_r2kl[m][hi * 32 + tl] = s5;

        r2v[0][d][tl] = s0; r2v[1][d][tl] = s1; r2v[2][d][tl] = s2;
        r2v[3][d][tl] = s3; r2v[4][d][tl] = s4; r2v[5][d][tl] = s5;
        __syncthreads();

        int tlp = t >> 3, so = t & 7;
        float b0 = 0.f, b1 = 0.f, b2 = 0.f, b3 = 0.f, b4 = 0.f, b5 = 0.f;
#pragma unroll
        for (int a = 0; a < 6; ++a)
#pragma unroll
            for (int dd = 0; dd < 8; ++dd) {
                float v = r2v[a][dd][tlp];
                float4 c0 = CT[a][dd][so][0];
                float4 c1 = CT[a][dd][so][1];
                b0 += v * c0.x; b1 += v * c0.y; b2 += v * c0.z;
                b3 += v * c0.w; b4 += v * c1.x; b5 += v * c1.y;
            }
        int tt = hi * 32 + tlp;
        g_g2[0][n][so][tt] = b0; g_g2[1][n][so][tt] = b1;
        g_g2[2][n][so][tt] = b2; g_g2[3][n][so][tt] = b3;
        g_g2[4][n][so][tt] = b4; g_g2[5][n][so][tt] = b5;
    }
}

// ---------------------------------------------------------------------------
// Kf (exact R15 form): block per (n, i, j-quad), grid 256.
// ---------------------------------------------------------------------------
__global__ void __launch_bounds__(256, 2) k_final(const float* __restrict__ x,
                                                  const float* __restrict__ coefs,
                                                  const float* __restrict__ bias,
                                                  float* __restrict__ out) {
    extern __shared__ __align__(16) char sm[];
    float4* sV  = reinterpret_cast<float4*>(sm);            // [8][256]
    float*  P8  = reinterpret_cast<float*>(sm + 32768);     // [8][8][32]
    float*  Q8  = reinterpret_cast<float*>(sm + 40960);     // [8][8][32]
    float*  sg1 = reinterpret_cast<float*>(sm + 49152);     // [4][8][32]
    float*  sr1 = reinterpret_cast<float*>(sm + 53248);     // [4][8][32]
    float*  cf  = reinterpret_cast<float*>(sm + 57344);     // [8][8]

    int bid = blockIdx.x;
    int n = bid >> 7, i = (bid >> 2) & 31, jq = bid & 3;
    int t = threadIdx.x, k = t >> 3, lq = t & 7;

    {
        int d = t >> 5, v = t & 31, m = n * 8 + d;
        float s = 0.f;
#pragma unroll
        for (int kk = 0; kk < 32; ++kk) s += __ldg(&g_r2kl[m][kk * 32 + v]);
        sr1[(3 * 8 + d) * 32 + v] = s;
        sr1[(0 * 8 + d) * 32 + v] = __ldg(&g_r1raw[0][m][v]);
        sr1[(1 * 8 + d) * 32 + v] = __ldg(&g_r1raw[1][m][v]);
        sr1[(2 * 8 + d) * 32 + v] = __ldg(&g_r1raw[2][m][v]);
    }
    if (t < 64) cf[t] = __ldg(&coefs[(t >> 3) * 552 + (t & 7) * 69 + 68]);
    __syncthreads();

    {
        int so = t >> 5, v = t & 31;
        float b0 = 0.f, b1 = 0.f, b2 = 0.f, b3 = 0.f;
#pragma unroll
        for (int a = 0; a < 4; ++a)
#pragma unroll
            for (int d = 0; d < 8; ++d) {
                float val = sr1[(a * 8 + d) * 32 + v];
                const float* cp = &coefs[d * 552 + so * 69 + a * 4];
                b0 += __ldg(cp + 0) * val;
                b1 += __ldg(cp + 1) * val;
                b2 += __ldg(cp + 2) * val;
                b3 += __ldg(cp + 3) * val;
            }
        sg1[(0 * 8 + so) * 32 + v] = b0;
        sg1[(1 * 8 + so) * 32 + v] = b1;
        sg1[(2 * 8 + so) * 32 + v] = b2;
        sg1[(3 * 8 + so) * 32 + v] = b3;
    }
    __syncthreads();

#pragma unroll
    for (int so = 0; so < 8; ++so) {
        float4 a = __ldg(reinterpret_cast<const float4*>(g_g3[2][n][so]) + i * 256 + t);
        float4 b = __ldg(reinterpret_cast<const float4*>(g_g2[5][n][so]) + t);
        a.x += b.x; a.y += b.y; a.z += b.z; a.w += b.w;
        sV[so * 256 + t] = a;
    }
    {
        int jj = t >> 5, kk = t & 31;
        int j = jq * 8 + jj, ij = i * 32 + j;
#pragma unroll
        for (int so = 0; so < 8; ++so) {
            P8[(jj * 8 + so) * 32 + kk] =
                  __ldg(&g_g3[0][n][so][ij * 32 + kk])
                + __ldg(&g_g2[3][n][so][j * 32 + kk])
                + __ldg(&g_g2[1][n][so][i * 32 + kk])
                + sg1[(2 * 8 + so) * 32 + kk]
                + __ldg(&g_g2[0][n][so][ij])
                + sg1[(0 * 8 + so) * 32 + i]
                + sg1[(1 * 8 + so) * 32 + j]
                + __ldg(&bias[so]);
            Q8[(jj * 8 + so) * 32 + kk] =
                  __ldg(&g_g3[1][n][so][ij * 32 + kk])
                + __ldg(&g_g2[4][n][so][j * 32 + kk])
                + __ldg(&g_g2[2][n][so][i * 32 + kk])
                + sg1[(3 * 8 + so) * 32 + kk];
        }
    }
    __syncthreads();

    const float4* xb = reinterpret_cast<const float4*>(x);
    float4* ob = reinterpret_cast<float4*>(out);

    for (int jj = 0; jj < 8; ++jj) {
        int j = jq * 8 + jj;
        int plane = (i * 32 + j) * 256 + t;

        float4 xv[8];
#pragma unroll
        for (int d = 0; d < 8; ++d)
            xv[d] = __ldg(xb + (size_t)(n * 8 + d) * (N4 / 4) + plane);
        float4 a4[8];
#pragma unroll
        for (int so = 0; so < 8; ++so)
            a4[so] = __ldg(reinterpret_cast<const float4*>(g_g3[3][n][so]) + j * 256 + t);

#pragma unroll
        for (int so = 0; so < 8; ++so) {
            float4 v1 = sV[so * 256 + t];
            float base = P8[(jj * 8 + so) * 32 + k];
            float4 q = *reinterpret_cast<const float4*>(&Q8[(jj * 8 + so) * 32 + lq * 4]);

            float4 acc;
            acc.x = base + q.x + v1.x + a4[so].x;
            acc.y = base + q.y + v1.y + a4[so].y;
            acc.z = base + q.z + v1.z + a4[so].z;
            acc.w = base + q.w + v1.w + a4[so].w;
#pragma unroll
            for (int d = 0; d < 8; ++d) {
                float c = cf[d * 8 + so];
                acc.x += c * xv[d].x;
                acc.y += c * xv[d].y;
                acc.z += c * xv[d].z;
                acc.w += c * xv[d].w;
            }
            ob[(size_t)(n * 8 + so) * (N4 / 4) + plane] = acc;
        }
    }
}

extern "C" void kernel_launch(void* const* d_in, const int* in_sizes, int n_in,
                              void* d_out, int out_size) {
    const float* x     = (const float*)d_in[0];
    const float* coefs = (const float*)d_in[1];
    const float* bias  = (const float*)d_in[2];
    float* out = (float*)d_out;

    cudaFuncSetAttribute(k_final, cudaFuncAttributeMaxDynamicSharedMemorySize, 57600);

    k_pass1<<<1024, 256>>>(x);           // r3[0..3] + 5 raw r2 tables
    k_mid<<<192, 256>>>(coefs);          // g3 mix + g2/r1/r_kl (r2 half slimmed)
    k_final<<<256, 256, 57600>>>(x, coefs, bias, out);
}